// round 6
// baseline (speedup 1.0000x reference)
#include <cuda_runtime.h>
#include <cstdint>
#include <cstddef>

// ---------------------------------------------------------------------------
// LatticeLSTM forward.  B=64 T=512 X=8 DC=DW=H=128.
// Phase 1: three dense GEMMs (input projections) -> __device__ scratch.
// Phase 2: persistent recurrent kernel, one CTA per batch, 512 steps.
// Key optimization: h-history is stored PRE-PROJECTED by w_hh_w, so skip
// gathers read a [384] vector instead of redoing an 8x384x128 GEMM per step.
// ---------------------------------------------------------------------------

#define BB 64
#define TT 512
#define XX 8
#define HH 128
#define G3 384   // 3*H

// Scratch (zero-initialized at module load; contents re-written every run)
__device__ float g_wic[(size_t)BB * TT * G3];            // inp @ w_ih_c + bias_c
__device__ float g_awi[(size_t)BB * TT * HH];            // inp @ a_ih + a_bias
__device__ float g_wiw[(size_t)BB * TT * XX * G3];       // skip_words @ w_ih_w + bias_w
__device__ float g_hw [(size_t)BB * (TT + 1) * G3];      // h_hist[i] @ w_hh_w

// ---------------- packed f32x2 helpers --------------------------------------
__device__ __forceinline__ unsigned long long pk2(float x, float y) {
    unsigned long long r;
    asm("mov.b64 %0, {%1, %2};" : "=l"(r) : "f"(x), "f"(y));
    return r;
}
__device__ __forceinline__ void ffma2(unsigned long long& d,
                                      unsigned long long a, unsigned long long b) {
    asm("fma.rn.f32x2 %0, %1, %2, %0;" : "+l"(d) : "l"(a), "l"(b));
}
__device__ __forceinline__ void unpk2(unsigned long long v, float& lo, float& hi) {
    asm("mov.b64 {%0, %1}, %2;" : "=f"(lo), "=f"(hi) : "l"(v));
}

__device__ __forceinline__ float fsig(float x) {
    return __fdividef(1.0f, 1.0f + __expf(-x));
}
__device__ __forceinline__ float ftanh(float x) {
    return 1.0f - __fdividef(2.0f, __expf(2.0f * x) + 1.0f);
}

// ---------------------------------------------------------------------------
// GEMM: C[M x Nw] = A[M x 128] * W[128 x Nw] + bias[Nw]
// BM=BN=BK=128, 256 threads, 8x8 micro-tile via f32x2 (8 rows x 4 col-pairs).
// M, Nw multiples of 128.
// ---------------------------------------------------------------------------
__global__ __launch_bounds__(256, 1)
void gemm128_kernel(const float* __restrict__ A, const float* __restrict__ W,
                    const float* __restrict__ bias, float* __restrict__ C, int Nw)
{
    extern __shared__ float sm[];
    float* As = sm;          // [k][m]  128*128
    float* Bs = sm + 16384;  // [k][n]  128*128

    const int tid = threadIdx.x;
    const size_t m0 = (size_t)blockIdx.x * 128;
    const int n0 = blockIdx.y * 128;

    // Load A tile (transposed into As[k][m])
#pragma unroll
    for (int i = 0; i < 16; ++i) {
        int f = tid + i * 256;          // 0..4095
        int row = f & 127, k4 = f >> 7; // k4: 0..31
        float4 v = *(const float4*)(A + (m0 + row) * 128 + k4 * 4);
        As[(k4 * 4 + 0) * 128 + row] = v.x;
        As[(k4 * 4 + 1) * 128 + row] = v.y;
        As[(k4 * 4 + 2) * 128 + row] = v.z;
        As[(k4 * 4 + 3) * 128 + row] = v.w;
    }
    // Load W tile (Bs[k][n])
#pragma unroll
    for (int i = 0; i < 16; ++i) {
        int f = tid + i * 256;
        int n4 = f & 31, k = f >> 5;
        float4 v = *(const float4*)(W + (size_t)k * Nw + n0 + n4 * 4);
        *(float4*)(Bs + k * 128 + n4 * 4) = v;
    }
    __syncthreads();

    const int tx = tid & 15, ty = tid >> 4;
    const int mr = ty * 8, nc = tx * 8;

    unsigned long long acc[8][4];
#pragma unroll
    for (int i = 0; i < 8; ++i)
#pragma unroll
        for (int j = 0; j < 4; ++j) acc[i][j] = 0ull;

#pragma unroll 4
    for (int k = 0; k < 128; ++k) {
        unsigned long long b2[4];
#pragma unroll
        for (int j = 0; j < 4; ++j)
            b2[j] = *(const unsigned long long*)(Bs + k * 128 + nc + 2 * j);
#pragma unroll
        for (int i = 0; i < 8; ++i) {
            float a = As[k * 128 + mr + i];
            unsigned long long a2 = pk2(a, a);
#pragma unroll
            for (int j = 0; j < 4; ++j) ffma2(acc[i][j], a2, b2[j]);
        }
    }

    // Epilogue
#pragma unroll
    for (int i = 0; i < 8; ++i) {
        size_t row = m0 + mr + i;
#pragma unroll
        for (int j = 0; j < 4; ++j) {
            float lo, hi;
            unpk2(acc[i][j], lo, hi);
            int n = n0 + nc + 2 * j;
            float2 o;
            o.x = lo + bias[n];
            o.y = hi + bias[n + 1];
            *(float2*)(C + row * Nw + n) = o;
        }
    }
}

// ---------------------------------------------------------------------------
// Recurrent kernel: one CTA per batch, 256 threads, 512 sequential steps.
// smem: w_hh_w (196KB) + buffers.
// ---------------------------------------------------------------------------
#define SMEM_REC (49152 + 384 + 128 + 1024 + 256 + 256) /* floats */

__global__ __launch_bounds__(256, 1)
void lattice_rec_kernel(const float* __restrict__ w_hh_w,
                        const float* __restrict__ w_hh_c,
                        const float* __restrict__ a_hh,
                        const int*   __restrict__ src_all,
                        const int*   __restrict__ cnt_all,
                        float*       __restrict__ out)
{
    extern __shared__ float sm[];
    float* sWw = sm;                  // [k*384 + c]  w_hh_w resident
    float* hcc = sWw + 49152;         // 384: h_prev @ w_hh_c
    float* h1s = hcc + 384;           // 128
    float* c1s = h1s + 128;           // [x][h] 8*128
    float* sPE = c1s + 1024;          // [2][128] partial exp sums
    float* sPM = sPE + 256;           // [2][128] partial weighted sums

    const int b = blockIdx.x;
    const int tid = threadIdx.x;
    float* hs_out = out;
    float* cs_out = out + (size_t)BB * TT * HH;

    // Cache w_hh_w in smem; zero hcc (h_hist[0] = 0)
    for (int i = tid; i < 49152 / 4; i += 256)
        ((float4*)sWw)[i] = ((const float4*)w_hh_w)[i];
    for (int c = tid; c < 384; c += 256) hcc[c] = 0.0f;
    __syncthreads();

    const int x8 = tid >> 5;       // skip slot handled in phase A (0..7)
    const int lane = tid & 31;
    const int hq = tid & 127;      // h' handled in phase C
    const int xg = tid >> 7;       // x-group 0/1 in phase C

    for (int t = 0; t < TT; ++t) {
        // ---- Phase A: gather pre-projected history, compute c1_skip -------
        {
            int sx = src_all[(b * TT + t) * XX + x8];
            const float* hwrow = g_hw  + ((size_t)(b * (TT + 1) + sx + 1)) * G3;
            const float* wrow  = g_wiw + ((size_t)((b * TT + t) * XX + x8)) * G3;
            const float* cxrow = cs_out + ((size_t)(b * TT + sx)) * HH;
#pragma unroll
            for (int j = 0; j < 4; ++j) {
                int h = lane + 32 * j;
                float fg = fsig (hwrow[h]       + wrow[h]);
                float ig = fsig (hwrow[128 + h] + wrow[128 + h]);
                float gg = ftanh(hwrow[256 + h] + wrow[256 + h]);
                c1s[x8 * 128 + h] = fg * cxrow[h] + ig * gg;
            }
        }
        __syncthreads();

        // ---- Phase C1: aat = c1_skip @ a_hh, masked exp partials ----------
        {
            const float* cbase = c1s + xg * 4 * 128;
            float a0 = 0.f, a1 = 0.f, a2 = 0.f, a3 = 0.f;
#pragma unroll 8
            for (int h = 0; h < 128; ++h) {
                float a = __ldg(a_hh + h * 128 + hq);
                a0 += cbase[h]       * a;
                a1 += cbase[128 + h] * a;
                a2 += cbase[256 + h] * a;
                a3 += cbase[384 + h] * a;
            }
            int cv = cnt_all[b * TT + t];
            float awi = g_awi[((size_t)(b * TT + t)) * HH + hq];
            float accs[4] = {a0, a1, a2, a3};
            float pe = 0.f, pm = 0.f;
#pragma unroll
            for (int xi = 0; xi < 4; ++xi) {
                int x = xg * 4 + xi;
                float e = (x < cv) ? __expf(fsig(awi + accs[xi])) : 0.0f;
                pe += e;
                pm += e * c1s[x * 128 + hq];
            }
            sPE[xg * 128 + hq] = pe;
            sPM[xg * 128 + hq] = pm;
        }
        __syncthreads();

        // ---- Phase C2: main-cell gates, softmax merge, outputs ------------
        if (tid < 128) {
            const float* wic = g_wic + ((size_t)(b * TT + t)) * G3;
            float gci = hcc[tid]       + wic[tid];        // i gate
            float gco = hcc[128 + tid] + wic[128 + tid];  // o gate
            float gcg = hcc[256 + tid] + wic[256 + tid];  // g
            float e0 = __expf(fsig(gci));
            float gg = ftanh(gcg);
            float denom = e0 + sPE[tid] + sPE[128 + tid];
            float c1 = __fdividef(e0 * gg + sPM[tid] + sPM[128 + tid], denom);
            float h1 = fsig(gco) * ftanh(c1);
            h1s[tid] = h1;
            size_t o = ((size_t)(b * TT + t)) * HH + tid;
            hs_out[o] = h1;
            cs_out[o] = c1;
        }
        __syncthreads();

        // ---- Phase D: project h1 by w_hh_w (-> history) and w_hh_c --------
        {
            float acc0 = 0.f, acc1 = 0.f, acc2 = 0.f;
            if (tid < 128) {
                const float* wA = sWw + tid;            // smem col tid
                const float* wB = sWw + tid + 256;      // smem col tid+256
                const float* wC = w_hh_c + tid + 128;   // global col tid+128
#pragma unroll 8
                for (int k = 0; k < 128; ++k) {
                    float hb = h1s[k];
                    acc0 += hb * wA[k * G3];
                    acc1 += hb * wB[k * G3];
                    acc2 += hb * __ldg(wC + k * G3);
                }
                float* hwdst = g_hw + ((size_t)(b * (TT + 1) + t + 1)) * G3;
                hwdst[tid] = acc0;
                hwdst[tid + 256] = acc1;
                hcc[tid + 128] = acc2;
            } else {
                int u = tid - 128;
                const float* wA = sWw + tid;            // smem col tid (128..255)
                const float* wB = w_hh_c + u;           // global col u
                const float* wC = w_hh_c + u + 256;     // global col u+256
#pragma unroll 8
                for (int k = 0; k < 128; ++k) {
                    float hb = h1s[k];
                    acc0 += hb * wA[k * G3];
                    acc1 += hb * __ldg(wB + k * G3);
                    acc2 += hb * __ldg(wC + k * G3);
                }
                g_hw[((size_t)(b * (TT + 1) + t + 1)) * G3 + tid] = acc0;
                hcc[u] = acc1;
                hcc[u + 256] = acc2;
            }
        }
        __syncthreads();
    }
}

// ---------------------------------------------------------------------------
extern "C" void kernel_launch(void* const* d_in, const int* in_sizes, int n_in,
                              void* d_out, int out_size)
{
    const float *inp = nullptr, *skip_words = nullptr;
    const float *w_ih_c = nullptr, *w_hh_c = nullptr, *bias_c = nullptr;
    const float *a_ih = nullptr, *a_hh = nullptr, *a_bias = nullptr;
    const float *w_ih_w = nullptr, *w_hh_w = nullptr, *bias_w = nullptr;
    const int *skip_sources = nullptr, *skip_count = nullptr;

    int c49 = 0, c384 = 0, c16 = 0;
    for (int i = 0; i < n_in; ++i) {
        switch (in_sizes[i]) {
            case 4194304:  inp = (const float*)d_in[i]; break;
            case 33554432: skip_words = (const float*)d_in[i]; break;
            case 64:       /* seq_len, unused */ break;
            case 262144:   skip_sources = (const int*)d_in[i]; break;
            case 32768:    skip_count = (const int*)d_in[i]; break;
            case 49152:
                if (c49 == 0) w_ih_c = (const float*)d_in[i];
                else if (c49 == 1) w_hh_c = (const float*)d_in[i];
                else if (c49 == 2) w_ih_w = (const float*)d_in[i];
                else w_hh_w = (const float*)d_in[i];
                ++c49; break;
            case 384:
                if (c384 == 0) bias_c = (const float*)d_in[i];
                else bias_w = (const float*)d_in[i];
                ++c384; break;
            case 16384:
                if (c16 == 0) a_ih = (const float*)d_in[i];
                else a_hh = (const float*)d_in[i];
                ++c16; break;
            case 128:      a_bias = (const float*)d_in[i]; break;
            default: break;
        }
    }

    void *p_wic = nullptr, *p_awi = nullptr, *p_wiw = nullptr;
    cudaGetSymbolAddress(&p_wic, g_wic);
    cudaGetSymbolAddress(&p_awi, g_awi);
    cudaGetSymbolAddress(&p_wiw, g_wiw);

    cudaFuncSetAttribute(gemm128_kernel,
                         cudaFuncAttributeMaxDynamicSharedMemorySize, 131072);
    cudaFuncSetAttribute(lattice_rec_kernel,
                         cudaFuncAttributeMaxDynamicSharedMemorySize,
                         SMEM_REC * (int)sizeof(float));

    // Input projections (time-independent)
    gemm128_kernel<<<dim3(256, 3),  256, 131072>>>(inp, w_ih_c, bias_c,
                                                   (float*)p_wic, 384);
    gemm128_kernel<<<dim3(256, 1),  256, 131072>>>(inp, a_ih, a_bias,
                                                   (float*)p_awi, 128);
    gemm128_kernel<<<dim3(2048, 3), 256, 131072>>>(skip_words, w_ih_w, bias_w,
                                                   (float*)p_wiw, 384);

    // Recurrence: one CTA per batch
    lattice_rec_kernel<<<BB, 256, SMEM_REC * sizeof(float)>>>(
        w_hh_w, w_hh_c, a_hh, skip_sources, skip_count, (float*)d_out);
}

// round 10
// speedup vs baseline: 1.9528x; 1.9528x over previous
#include <cuda_runtime.h>
#include <cstdint>
#include <cstddef>

// ---------------------------------------------------------------------------
// LatticeLSTM forward.  B=64 T=512 X=8 DC=DW=H=128.
// Phase 1: three dense GEMMs (input projections) -> __device__ scratch.
// Phase 2: cluster-2 persistent recurrent kernel: 2 CTAs per batch.
//   rank0 holds w_hh_w (cols 0..255 in regs, 256..383 in smem)
//   rank1 holds w_hh_c (same split)
//   a_hh lives in smem on both ranks.
//   Phases A (c1_skip) and C1 (aat) are split 4 skip-rows per rank with a
//   DSMEM partial exchange; C2 is redundant; D is the register GEMV.
// ---------------------------------------------------------------------------

#define BB 64
#define TT 512
#define XX 8
#define HH 128
#define G3 384   // 3*H

// Scratch
__device__ float g_wic[(size_t)BB * TT * G3];            // inp @ w_ih_c + bias_c
__device__ float g_awi[(size_t)BB * TT * HH];            // inp @ a_ih + a_bias
__device__ float g_wiw[(size_t)BB * TT * XX * G3];       // skip_words @ w_ih_w + bias_w
__device__ float g_hw [(size_t)BB * (TT + 1) * G3];      // h_hist[i] @ w_hh_w

// ---------------- packed f32x2 helpers (GEMM) --------------------------------
__device__ __forceinline__ unsigned long long pk2(float x, float y) {
    unsigned long long r;
    asm("mov.b64 %0, {%1, %2};" : "=l"(r) : "f"(x), "f"(y));
    return r;
}
__device__ __forceinline__ void ffma2(unsigned long long& d,
                                      unsigned long long a, unsigned long long b) {
    asm("fma.rn.f32x2 %0, %1, %2, %0;" : "+l"(d) : "l"(a), "l"(b));
}
__device__ __forceinline__ void unpk2(unsigned long long v, float& lo, float& hi) {
    asm("mov.b64 {%0, %1}, %2;" : "=f"(lo), "=f"(hi) : "l"(v));
}

__device__ __forceinline__ float fsig(float x) {
    return __fdividef(1.0f, 1.0f + __expf(-x));
}
__device__ __forceinline__ float ftanh(float x) {
    return 1.0f - __fdividef(2.0f, __expf(2.0f * x) + 1.0f);
}

// ---------------- cluster / DSMEM helpers ------------------------------------
__device__ __forceinline__ uint32_t smem_u32(const void* p) {
    uint32_t a;
    asm("{ .reg .u64 t; cvta.to.shared.u64 t, %1; cvt.u32.u64 %0, t; }"
        : "=r"(a) : "l"(p));
    return a;
}
__device__ __forceinline__ uint32_t mapa_rank(uint32_t a, uint32_t r) {
    uint32_t o;
    asm("mapa.shared::cluster.u32 %0, %1, %2;" : "=r"(o) : "r"(a), "r"(r));
    return o;
}
__device__ __forceinline__ void st_remote(uint32_t a, float v) {
    asm volatile("st.shared::cluster.f32 [%0], %1;" :: "r"(a), "f"(v) : "memory");
}
#define CLUSTER_SYNC() do { \
    asm volatile("barrier.cluster.arrive.aligned;" ::: "memory"); \
    asm volatile("barrier.cluster.wait.aligned;"   ::: "memory"); \
} while (0)

// ---------------------------------------------------------------------------
// GEMM: C[M x Nw] = A[M x 128] * W[128 x Nw] + bias[Nw]  (unchanged, passing)
// ---------------------------------------------------------------------------
__global__ __launch_bounds__(256, 1)
void gemm128_kernel(const float* __restrict__ A, const float* __restrict__ W,
                    const float* __restrict__ bias, float* __restrict__ C, int Nw)
{
    extern __shared__ float sm[];
    float* As = sm;          // [k][m]
    float* Bs = sm + 16384;  // [k][n]

    const int tid = threadIdx.x;
    const size_t m0 = (size_t)blockIdx.x * 128;
    const int n0 = blockIdx.y * 128;

#pragma unroll
    for (int i = 0; i < 16; ++i) {
        int f = tid + i * 256;
        int row = f & 127, k4 = f >> 7;
        float4 v = *(const float4*)(A + (m0 + row) * 128 + k4 * 4);
        As[(k4 * 4 + 0) * 128 + row] = v.x;
        As[(k4 * 4 + 1) * 128 + row] = v.y;
        As[(k4 * 4 + 2) * 128 + row] = v.z;
        As[(k4 * 4 + 3) * 128 + row] = v.w;
    }
#pragma unroll
    for (int i = 0; i < 16; ++i) {
        int f = tid + i * 256;
        int n4 = f & 31, k = f >> 5;
        float4 v = *(const float4*)(W + (size_t)k * Nw + n0 + n4 * 4);
        *(float4*)(Bs + k * 128 + n4 * 4) = v;
    }
    __syncthreads();

    const int tx = tid & 15, ty = tid >> 4;
    const int mr = ty * 8, nc = tx * 8;

    unsigned long long acc[8][4];
#pragma unroll
    for (int i = 0; i < 8; ++i)
#pragma unroll
        for (int j = 0; j < 4; ++j) acc[i][j] = 0ull;

#pragma unroll 4
    for (int k = 0; k < 128; ++k) {
        unsigned long long b2[4];
#pragma unroll
        for (int j = 0; j < 4; ++j)
            b2[j] = *(const unsigned long long*)(Bs + k * 128 + nc + 2 * j);
#pragma unroll
        for (int i = 0; i < 8; ++i) {
            float a = As[k * 128 + mr + i];
            unsigned long long a2 = pk2(a, a);
#pragma unroll
            for (int j = 0; j < 4; ++j) ffma2(acc[i][j], a2, b2[j]);
        }
    }

#pragma unroll
    for (int i = 0; i < 8; ++i) {
        size_t row = m0 + mr + i;
#pragma unroll
        for (int j = 0; j < 4; ++j) {
            float lo, hi;
            unpk2(acc[i][j], lo, hi);
            int n = n0 + nc + 2 * j;
            float2 o;
            o.x = lo + bias[n];
            o.y = hi + bias[n + 1];
            *(float2*)(C + row * Nw + n) = o;
        }
    }
}

// ---------------------------------------------------------------------------
// Recurrent kernel: cluster of 2 CTAs per batch, 256 threads each.
// smem (floats): sA 16384 | sW2 16384 | c1s 1024 | sPE 512 | sPM 512 |
//                hccA 384 | hccB 384 | h1s 128  = 35712 floats = 142848 B
// ---------------------------------------------------------------------------
#define SMEM_REC_FLOATS 35712

__global__ __launch_bounds__(256, 1) __cluster_dims__(2, 1, 1)
void lattice_rec_kernel(const float* __restrict__ w_hh_w,
                        const float* __restrict__ w_hh_c,
                        const float* __restrict__ a_hh,
                        const int*   __restrict__ src_all,
                        const int*   __restrict__ cnt_all,
                        float*       __restrict__ out)
{
    extern __shared__ float sm[];
    float* sA   = sm;              // a_hh [k][h]
    float* sW2  = sm + 16384;      // spill weight cols 256..383, [k][c]
    float* c1s  = sm + 32768;      // [x][h]
    float* sPE  = sm + 33792;      // [4][128]
    float* sPM  = sm + 34304;      // [4][128]
    float* hccA = sm + 34816;      // 384 (h_prev @ w_hh_c), parity buffers
    float* hccB = sm + 35200;
    float* h1s  = sm + 35584;      // 128

    const int tid = threadIdx.x;
    uint32_t rank;
    asm("mov.u32 %0, %%cluster_ctarank;" : "=r"(rank));
    const int b = blockIdx.x >> 1;

    float* hs_out = out;
    float* cs_out = out + (size_t)BB * TT * HH;

    const float* Wsel = rank ? w_hh_c : w_hh_w;

    // Register-resident weight column `tid` of Wsel (cols 0..255)
    float wr[128];
#pragma unroll
    for (int k = 0; k < 128; ++k) wr[k] = Wsel[k * G3 + tid];

    // Spill cols 256..383 into smem [k][c]
    for (int f = tid; f < 16384; f += 256) {
        int c = f & 127, k = f >> 7;
        sW2[k * 128 + c] = Wsel[k * G3 + 256 + c];
    }
    // a_hh -> smem
    for (int i = tid; i < 4096; i += 256)
        ((float4*)sA)[i] = ((const float4*)a_hh)[i];
    for (int i = tid; i < 384; i += 256) { hccA[i] = 0.0f; hccB[i] = 0.0f; }
    __syncthreads();

    const int hq   = tid & 127;          // h index for C1/C2/D-pass2
    const int half = tid >> 7;           // x-pair within rank's 4 rows
    const int xa   = rank * 4 + (tid >> 6);  // phase-A skip row (rank-local split)
    const int ha   = tid & 63;               // phase-A h base (ha, ha+64)

    // ---- Prefetch registers (step t's pure-input streams) ------------------
    int   psx, pcv;
    float pwf0, pwf1, pwi0, pwi1, pwg0, pwg1;
    float pcx0, pcx1, pawi, pc2i, pc2o, pc2g;
    {
        psx = src_all[(b * TT + 0) * XX + xa];
        const float* wrow = g_wiw + ((size_t)((b * TT + 0) * XX + xa)) * G3;
        pwf0 = wrow[ha];        pwf1 = wrow[ha + 64];
        pwi0 = wrow[128 + ha];  pwi1 = wrow[128 + ha + 64];
        pwg0 = wrow[256 + ha];  pwg1 = wrow[256 + ha + 64];
        const float* cx = cs_out + ((size_t)(b * TT + psx)) * HH;
        pcx0 = cx[ha]; pcx1 = cx[ha + 64];   // t=0: garbage, fully masked
        pcv  = cnt_all[b * TT + 0];
        pawi = g_awi[((size_t)(b * TT + 0)) * HH + hq];
        const float* wic = g_wic + ((size_t)(b * TT + 0)) * G3;
        pc2i = wic[hq]; pc2o = wic[128 + hq]; pc2g = wic[256 + hq];
    }

    const uint32_t peer = rank ^ 1u;

    for (int t = 0; t < TT; ++t) {
        const float* hcc_r = (t & 1) ? hccB : hccA;   // read buffer
        float*       hcc_w = (t & 1) ? hccA : hccB;   // write buffer (for t+1)

        // ---- Phase A (split by rank): c1_skip for rows xa ------------------
        {
            const float* hwrow = g_hw + ((size_t)(b * (TT + 1) + psx + 1)) * G3;
            float f0 = fsig (hwrow[ha]           + pwf0);
            float f1 = fsig (hwrow[ha + 64]      + pwf1);
            float i0 = fsig (hwrow[128 + ha]     + pwi0);
            float i1 = fsig (hwrow[128 + ha + 64]+ pwi1);
            float g0 = ftanh(hwrow[256 + ha]     + pwg0);
            float g1 = ftanh(hwrow[256 + ha + 64]+ pwg1);
            c1s[xa * 128 + ha]      = f0 * pcx0 + i0 * g0;
            c1s[xa * 128 + ha + 64] = f1 * pcx1 + i1 * g1;
        }
        __syncthreads();

        // ---- Phase C1 (split by rank): aat + masked exp partials -----------
        {
            const int x0 = rank * 4 + half * 2;
            const float* r0 = c1s + x0 * 128;
            const float* r1 = r0 + 128;
            float a0 = 0.f, a1 = 0.f;
#pragma unroll 16
            for (int k = 0; k < 128; ++k) {
                float a = sA[k * 128 + hq];
                a0 += r0[k] * a;
                a1 += r1[k] * a;
            }
            float e0 = (x0     < pcv) ? __expf(fsig(pawi + a0)) : 0.0f;
            float e1 = (x0 + 1 < pcv) ? __expf(fsig(pawi + a1)) : 0.0f;
            float pe = e0 + e1;
            float pm = e0 * r0[hq] + e1 * r1[hq];
            int slot = (rank * 2 + half) * 128 + hq;
            sPE[slot] = pe;
            sPM[slot] = pm;
            st_remote(mapa_rank(smem_u32(sPE + slot), peer), pe);
            st_remote(mapa_rank(smem_u32(sPM + slot), peer), pm);
        }
        CLUSTER_SYNC();   // partials visible on both ranks

        // ---- Phase C2 (redundant): gates, softmax merge, outputs -----------
        if (tid < 128) {
            float gci = hcc_r[tid]       + pc2i;
            float gco = hcc_r[128 + tid] + pc2o;
            float gcg = hcc_r[256 + tid] + pc2g;
            float e0 = __expf(fsig(gci));
            float gg = ftanh(gcg);
            float denom = e0 + sPE[tid] + sPE[128 + tid]
                             + sPE[256 + tid] + sPE[384 + tid];
            float num = e0 * gg + sPM[tid] + sPM[128 + tid]
                               + sPM[256 + tid] + sPM[384 + tid];
            float c1 = __fdividef(num, denom);
            float h1 = fsig(gco) * ftanh(c1);
            h1s[tid] = h1;
            size_t o = ((size_t)(b * TT + t)) * HH + tid;
            hs_out[o] = h1;   // both ranks store (keeps own L1 coherent)
            cs_out[o] = c1;
        }
        __syncthreads();

        // ---- Phase D: h1 @ Wsel (registers + smem spill) -------------------
        {
            float acc = 0.f;
            const float4* h4 = (const float4*)h1s;
#pragma unroll
            for (int k4 = 0; k4 < 32; ++k4) {
                float4 hv = h4[k4];
                acc += hv.x * wr[4 * k4]     + hv.y * wr[4 * k4 + 1]
                     + hv.z * wr[4 * k4 + 2] + hv.w * wr[4 * k4 + 3];
            }
            float acc2 = 0.f;
            if (tid < 128) {
#pragma unroll 16
                for (int k = 0; k < 128; ++k)
                    acc2 += h1s[k] * sW2[k * 128 + tid];
            }
            if (rank == 0) {
                float* dst = g_hw + ((size_t)(b * (TT + 1) + t + 1)) * G3;
                dst[tid] = acc;
                if (tid < 128) dst[256 + tid] = acc2;
            } else {
                hcc_w[tid] = acc;
                st_remote(mapa_rank(smem_u32(hcc_w + tid), 0u), acc);
                if (tid < 128) {
                    hcc_w[256 + tid] = acc2;
                    st_remote(mapa_rank(smem_u32(hcc_w + 256 + tid), 0u), acc2);
                }
            }
        }

        // ---- Prefetch t+1 (overlaps with cluster sync) ---------------------
        {
            int tn = (t + 1 < TT) ? t + 1 : t;
            psx = src_all[(b * TT + tn) * XX + xa];
            const float* wrow = g_wiw + ((size_t)((b * TT + tn) * XX + xa)) * G3;
            pwf0 = wrow[ha];        pwf1 = wrow[ha + 64];
            pwi0 = wrow[128 + ha];  pwi1 = wrow[128 + ha + 64];
            pwg0 = wrow[256 + ha];  pwg1 = wrow[256 + ha + 64];
            const float* cx = cs_out + ((size_t)(b * TT + psx)) * HH;
            pcx0 = cx[ha]; pcx1 = cx[ha + 64];   // row <= t: locally written
            pcv  = cnt_all[b * TT + tn];
            pawi = g_awi[((size_t)(b * TT + tn)) * HH + hq];
            const float* wic = g_wic + ((size_t)(b * TT + tn)) * G3;
            pc2i = wic[hq]; pc2o = wic[128 + hq]; pc2g = wic[256 + hq];
        }
        CLUSTER_SYNC();   // g_hw / hcc pushes visible for next step
    }
}

// ---------------------------------------------------------------------------
extern "C" void kernel_launch(void* const* d_in, const int* in_sizes, int n_in,
                              void* d_out, int out_size)
{
    const float *inp = nullptr, *skip_words = nullptr;
    const float *w_ih_c = nullptr, *w_hh_c = nullptr, *bias_c = nullptr;
    const float *a_ih = nullptr, *a_hh = nullptr, *a_bias = nullptr;
    const float *w_ih_w = nullptr, *w_hh_w = nullptr, *bias_w = nullptr;
    const int *skip_sources = nullptr, *skip_count = nullptr;

    int c49 = 0, c384 = 0, c16 = 0;
    for (int i = 0; i < n_in; ++i) {
        switch (in_sizes[i]) {
            case 4194304:  inp = (const float*)d_in[i]; break;
            case 33554432: skip_words = (const float*)d_in[i]; break;
            case 64:       /* seq_len, unused */ break;
            case 262144:   skip_sources = (const int*)d_in[i]; break;
            case 32768:    skip_count = (const int*)d_in[i]; break;
            case 49152:
                if (c49 == 0) w_ih_c = (const float*)d_in[i];
                else if (c49 == 1) w_hh_c = (const float*)d_in[i];
                else if (c49 == 2) w_ih_w = (const float*)d_in[i];
                else w_hh_w = (const float*)d_in[i];
                ++c49; break;
            case 384:
                if (c384 == 0) bias_c = (const float*)d_in[i];
                else bias_w = (const float*)d_in[i];
                ++c384; break;
            case 16384:
                if (c16 == 0) a_ih = (const float*)d_in[i];
                else a_hh = (const float*)d_in[i];
                ++c16; break;
            case 128:      a_bias = (const float*)d_in[i]; break;
            default: break;
        }
    }

    void *p_wic = nullptr, *p_awi = nullptr, *p_wiw = nullptr;
    cudaGetSymbolAddress(&p_wic, g_wic);
    cudaGetSymbolAddress(&p_awi, g_awi);
    cudaGetSymbolAddress(&p_wiw, g_wiw);

    cudaFuncSetAttribute(gemm128_kernel,
                         cudaFuncAttributeMaxDynamicSharedMemorySize, 131072);
    cudaFuncSetAttribute(lattice_rec_kernel,
                         cudaFuncAttributeMaxDynamicSharedMemorySize,
                         SMEM_REC_FLOATS * (int)sizeof(float));

    // Input projections (time-independent)
    gemm128_kernel<<<dim3(256, 3),  256, 131072>>>(inp, w_ih_c, bias_c,
                                                   (float*)p_wic, 384);
    gemm128_kernel<<<dim3(256, 1),  256, 131072>>>(inp, a_ih, a_bias,
                                                   (float*)p_awi, 128);
    gemm128_kernel<<<dim3(2048, 3), 256, 131072>>>(skip_words, w_ih_w, bias_w,
                                                   (float*)p_wiw, 384);

    // Recurrence: cluster of 2 CTAs per batch (128 CTAs, one wave)
    lattice_rec_kernel<<<BB * 2, 256, SMEM_REC_FLOATS * sizeof(float)>>>(
        w_hh_w, w_hh_c, a_hh, skip_sources, skip_count, (float*)d_out);
}

// round 11
// speedup vs baseline: 2.0756x; 1.0629x over previous
#include <cuda_runtime.h>
#include <cstdint>
#include <cstddef>

// ---------------------------------------------------------------------------
// LatticeLSTM forward.  B=64 T=512 X=8 DC=DW=H=128.
// Phase 1: three dense GEMMs (input projections) -> __device__ scratch.
// Phase 2: cluster-2 persistent recurrent kernel, 2 CTAs per batch.
//   rank0: w_hh_w (cols 0..255 in reg-pairs, 256..383 pair-packed in smem)
//   rank1: w_hh_c (same split)
//   a_hh transposed+padded in smem (f32x2-friendly).
//   Split arrive/wait cluster barriers with work in the windows; fresh hw row
//   pushed via DSMEM so phase A has zero global loads.
// ---------------------------------------------------------------------------

#define BB 64
#define TT 512
#define XX 8
#define HH 128
#define G3 384   // 3*H

__device__ float g_wic[(size_t)BB * TT * G3];
__device__ float g_awi[(size_t)BB * TT * HH];
__device__ float g_wiw[(size_t)BB * TT * XX * G3];
__device__ float g_hw [(size_t)BB * (TT + 1) * G3];

// ---------------- packed f32x2 helpers ---------------------------------------
__device__ __forceinline__ unsigned long long pk2(float x, float y) {
    unsigned long long r;
    asm("mov.b64 %0, {%1, %2};" : "=l"(r) : "f"(x), "f"(y));
    return r;
}
__device__ __forceinline__ void ffma2(unsigned long long& d,
                                      unsigned long long a, unsigned long long b) {
    asm("fma.rn.f32x2 %0, %1, %2, %0;" : "+l"(d) : "l"(a), "l"(b));
}
__device__ __forceinline__ void unpk2(unsigned long long v, float& lo, float& hi) {
    asm("mov.b64 {%0, %1}, %2;" : "=f"(lo), "=f"(hi) : "l"(v));
}

__device__ __forceinline__ float fsig(float x) {
    return __fdividef(1.0f, 1.0f + __expf(-x));
}
__device__ __forceinline__ float ftanh(float x) {
    return 1.0f - __fdividef(2.0f, __expf(2.0f * x) + 1.0f);
}

// ---------------- cluster / DSMEM helpers ------------------------------------
__device__ __forceinline__ uint32_t smem_u32(const void* p) {
    uint32_t a;
    asm("{ .reg .u64 t; cvta.to.shared.u64 t, %1; cvt.u32.u64 %0, t; }"
        : "=r"(a) : "l"(p));
    return a;
}
__device__ __forceinline__ uint32_t mapa_rank(uint32_t a, uint32_t r) {
    uint32_t o;
    asm("mapa.shared::cluster.u32 %0, %1, %2;" : "=r"(o) : "r"(a), "r"(r));
    return o;
}
__device__ __forceinline__ void st_remote(uint32_t a, float v) {
    asm volatile("st.shared::cluster.f32 [%0], %1;" :: "r"(a), "f"(v) : "memory");
}
__device__ __forceinline__ void st_remote64(uint32_t a, unsigned long long v) {
    asm volatile("st.shared::cluster.b64 [%0], %1;" :: "r"(a), "l"(v) : "memory");
}
#define CLUSTER_ARRIVE() asm volatile("barrier.cluster.arrive.aligned;" ::: "memory")
#define CLUSTER_WAIT()   asm volatile("barrier.cluster.wait.aligned;"   ::: "memory")

// ---------------------------------------------------------------------------
// GEMM: C[M x Nw] = A[M x 128] * W[128 x Nw] + bias[Nw]   (unchanged, passing)
// ---------------------------------------------------------------------------
__global__ __launch_bounds__(256, 1)
void gemm128_kernel(const float* __restrict__ A, const float* __restrict__ W,
                    const float* __restrict__ bias, float* __restrict__ C, int Nw)
{
    extern __shared__ float sm[];
    float* As = sm;
    float* Bs = sm + 16384;

    const int tid = threadIdx.x;
    const size_t m0 = (size_t)blockIdx.x * 128;
    const int n0 = blockIdx.y * 128;

#pragma unroll
    for (int i = 0; i < 16; ++i) {
        int f = tid + i * 256;
        int row = f & 127, k4 = f >> 7;
        float4 v = *(const float4*)(A + (m0 + row) * 128 + k4 * 4);
        As[(k4 * 4 + 0) * 128 + row] = v.x;
        As[(k4 * 4 + 1) * 128 + row] = v.y;
        As[(k4 * 4 + 2) * 128 + row] = v.z;
        As[(k4 * 4 + 3) * 128 + row] = v.w;
    }
#pragma unroll
    for (int i = 0; i < 16; ++i) {
        int f = tid + i * 256;
        int n4 = f & 31, k = f >> 5;
        float4 v = *(const float4*)(W + (size_t)k * Nw + n0 + n4 * 4);
        *(float4*)(Bs + k * 128 + n4 * 4) = v;
    }
    __syncthreads();

    const int tx = tid & 15, ty = tid >> 4;
    const int mr = ty * 8, nc = tx * 8;

    unsigned long long acc[8][4];
#pragma unroll
    for (int i = 0; i < 8; ++i)
#pragma unroll
        for (int j = 0; j < 4; ++j) acc[i][j] = 0ull;

#pragma unroll 4
    for (int k = 0; k < 128; ++k) {
        unsigned long long b2[4];
#pragma unroll
        for (int j = 0; j < 4; ++j)
            b2[j] = *(const unsigned long long*)(Bs + k * 128 + nc + 2 * j);
#pragma unroll
        for (int i = 0; i < 8; ++i) {
            float a = As[k * 128 + mr + i];
            unsigned long long a2 = pk2(a, a);
#pragma unroll
            for (int j = 0; j < 4; ++j) ffma2(acc[i][j], a2, b2[j]);
        }
    }

#pragma unroll
    for (int i = 0; i < 8; ++i) {
        size_t row = m0 + mr + i;
#pragma unroll
        for (int j = 0; j < 4; ++j) {
            float lo, hi;
            unpk2(acc[i][j], lo, hi);
            int n = n0 + nc + 2 * j;
            float2 o;
            o.x = lo + bias[n];
            o.y = hi + bias[n + 1];
            *(float2*)(C + row * Nw + n) = o;
        }
    }
}

// ---------------------------------------------------------------------------
// Recurrent kernel
// smem floats: sAT 16640 | sW2p 16384 | c1s 1024 | sPEM 1024 |
//              hccA 384 | hccB 384 | h1s 128 | hwfresh 384 = 36352 (145408 B)
// ---------------------------------------------------------------------------
#define SMEM_REC_FLOATS 36352

__global__ __launch_bounds__(256, 1) __cluster_dims__(2, 1, 1)
void lattice_rec_kernel(const float* __restrict__ w_hh_w,
                        const float* __restrict__ w_hh_c,
                        const float* __restrict__ a_hh,
                        const int*   __restrict__ src_all,
                        const int*   __restrict__ cnt_all,
                        float*       __restrict__ out)
{
    extern __shared__ float sm[];
    float* sAT  = sm;              // a_hh transposed [h][k], row pitch 130
    float* sW2p = sm + 16640;      // spill cols 256..383 pair-packed [k/2][c*2+(k&1)]
    float* c1s  = sm + 33024;      // [x][h]
    float* sPEM = sm + 34048;      // [(slot*128+h)*2] = (pe, pm)
    float* hccA = sm + 35072;      // 384, parity buffers
    float* hccB = sm + 35456;
    float* h1s  = sm + 35840;      // 128
    float* hwfresh = sm + 35968;   // 384: h1(t) @ w_hh_w, pushed by rank0

    const int tid = threadIdx.x;
    uint32_t rank;
    asm("mov.u32 %0, %%cluster_ctarank;" : "=r"(rank));
    const int b = blockIdx.x >> 1;
    const uint32_t peer = rank ^ 1u;

    float* hs_out = out;
    float* cs_out = out + (size_t)BB * TT * HH;

    const float* Wsel = rank ? w_hh_c : w_hh_w;

    // Register-resident weight col `tid` (cols 0..255), packed along k
    unsigned long long wrp[64];
#pragma unroll
    for (int j = 0; j < 64; ++j)
        wrp[j] = pk2(Wsel[(2 * j) * G3 + tid], Wsel[(2 * j + 1) * G3 + tid]);

    // Spill cols 256..383 pair-packed: sW2p[(k>>1)*256 + c*2 + (k&1)]
    for (int f = tid; f < 16384; f += 256) {
        int c = f & 127, k = f >> 7;
        sW2p[(k >> 1) * 256 + c * 2 + (k & 1)] = Wsel[k * G3 + 256 + c];
    }
    // a_hh transposed: sAT[h*130 + k] = a_hh[k*128 + h]
    for (int f = tid; f < 16384; f += 256) {
        int h = f & 127, k = f >> 7;
        sAT[h * 130 + k] = a_hh[f];
    }
    for (int i = tid; i < 384; i += 256) { hccA[i] = 0.0f; hccB[i] = 0.0f; }
    __syncthreads();

    const int hq   = tid & 127;
    const int half = tid >> 7;
    const int xa   = rank * 4 + (tid >> 6);
    const int ha   = tid & 63;
    const int x0   = rank * 4 + half * 2;

    // ---- prefetch registers ------------------------------------------------
    int   psx, pcv;
    bool  pfresh = false;
    float pwf0, pwf1, pwi0, pwi1, pwg0, pwg1;
    float pcx0, pcx1, pawi, pc2i, pc2o, pc2g;
    float phf0, phf1, phi0, phi1, phg0, phg1;
    {
        psx = src_all[(b * TT + 0) * XX + xa];
        const float* wrow = g_wiw + ((size_t)((b * TT + 0) * XX + xa)) * G3;
        pwf0 = wrow[ha];        pwf1 = wrow[ha + 64];
        pwi0 = wrow[128 + ha];  pwi1 = wrow[128 + ha + 64];
        pwg0 = wrow[256 + ha];  pwg1 = wrow[256 + ha + 64];
        const float* cx = cs_out + ((size_t)(b * TT + psx)) * HH;
        pcx0 = cx[ha]; pcx1 = cx[ha + 64];     // t=0: stale but fully masked
        pcv  = cnt_all[b * TT + 0];
        pawi = g_awi[((size_t)(b * TT + 0)) * HH + hq];
        const float* wic = g_wic + ((size_t)(b * TT + 0)) * G3;
        pc2i = wic[hq]; pc2o = wic[128 + hq]; pc2g = wic[256 + hq];
        const float* hwrow = g_hw + ((size_t)(b * (TT + 1) + psx + 1)) * G3;
        phf0 = hwrow[ha];        phf1 = hwrow[ha + 64];
        phi0 = hwrow[128 + ha];  phi1 = hwrow[128 + ha + 64];
        phg0 = hwrow[256 + ha];  phg1 = hwrow[256 + ha + 64];
    }

    for (int t = 0; t < TT; ++t) {
        const float* hcc_r = (t & 1) ? hccB : hccA;
        float*       hcc_w = (t & 1) ? hccA : hccB;

        // ---- Phase A: c1_skip for own rank's 4 rows (no global loads) ------
        {
            float F0, F1, I0, I1, G0, G1;
            if (pfresh) {
                F0 = hwfresh[ha];        F1 = hwfresh[ha + 64];
                I0 = hwfresh[128 + ha];  I1 = hwfresh[128 + ha + 64];
                G0 = hwfresh[256 + ha];  G1 = hwfresh[256 + ha + 64];
            } else {
                F0 = phf0; F1 = phf1; I0 = phi0; I1 = phi1; G0 = phg0; G1 = phg1;
            }
            float c0 = fsig(F0 + pwf0) * pcx0 + fsig(I0 + pwi0) * ftanh(G0 + pwg0);
            float c1x = fsig(F1 + pwf1) * pcx1 + fsig(I1 + pwi1) * ftanh(G1 + pwg1);
            c1s[xa * 128 + ha]      = c0;
            c1s[xa * 128 + ha + 64] = c1x;
        }
        __syncthreads();

        // ---- Phase C1: aat via f32x2, masked exp partials, packed push -----
        {
            const float* r0 = c1s + x0 * 128;
            const float* r1 = r0 + 128;
            const float* aT = sAT + hq * 130;
            unsigned long long ap0 = 0ull, ap1 = 0ull;
#pragma unroll 8
            for (int j = 0; j < 64; ++j) {
                unsigned long long a2 = *(const unsigned long long*)(aT + 2 * j);
                unsigned long long p0 = *(const unsigned long long*)(r0 + 2 * j);
                unsigned long long p1 = *(const unsigned long long*)(r1 + 2 * j);
                ffma2(ap0, a2, p0);
                ffma2(ap1, a2, p1);
            }
            float lo, hi;
            unpk2(ap0, lo, hi); float a0 = lo + hi;
            unpk2(ap1, lo, hi); float a1 = lo + hi;

            float e0 = (x0     < pcv) ? __expf(fsig(pawi + a0)) : 0.0f;
            float e1 = (x0 + 1 < pcv) ? __expf(fsig(pawi + a1)) : 0.0f;
            float pe = e0 + e1;
            float pm = e0 * r0[hq] + e1 * r1[hq];
            int slot = ((rank * 2 + half) * 128 + hq) * 2;
            unsigned long long pk = pk2(pe, pm);
            *(unsigned long long*)(sPEM + slot) = pk;
            st_remote64(mapa_rank(smem_u32(sPEM + slot), peer), pk);
        }
        CLUSTER_ARRIVE();

        // ---- C2a: partial-independent gate math in the sync window ---------
        float e0g = 0.f, ggg = 0.f, ogg = 0.f;
        if (tid < 128) {
            float gci = hcc_r[tid]       + pc2i;
            float gco = hcc_r[128 + tid] + pc2o;
            float gcg = hcc_r[256 + tid] + pc2g;
            e0g = __expf(fsig(gci));
            ogg = fsig(gco);
            ggg = ftanh(gcg);
        }
        CLUSTER_WAIT();

        // ---- C2b: merge, outputs -------------------------------------------
        if (tid < 128) {
            float pe = e0g, pm = e0g * ggg;
#pragma unroll
            for (int s = 0; s < 4; ++s) {
                float2 v = *(const float2*)(sPEM + (s * 128 + tid) * 2);
                pe += v.x;
                pm += v.y;
            }
            float c1v = __fdividef(pm, pe);
            float h1 = ogg * ftanh(c1v);
            h1s[tid] = h1;
            size_t o = ((size_t)(b * TT + t)) * HH + tid;
            hs_out[o] = h1;   // both ranks store (keeps own L1 coherent)
            cs_out[o] = c1v;
        }
        __syncthreads();

        // ---- Phase D: h1 @ Wsel, f32x2 reg + packed smem -------------------
        {
            unsigned long long accp = 0ull;
#pragma unroll
            for (int j = 0; j < 64; ++j) {
                unsigned long long hp = *(const unsigned long long*)(h1s + 2 * j);
                ffma2(accp, hp, wrp[j]);
            }
            float lo, hi;
            unpk2(accp, lo, hi);
            float acc = lo + hi;

            float acc2 = 0.f;
            if (tid < 128) {
                unsigned long long accq = 0ull;
                const float* wp = sW2p + 2 * tid;
#pragma unroll 8
                for (int j = 0; j < 64; ++j) {
                    unsigned long long hp = *(const unsigned long long*)(h1s + 2 * j);
                    unsigned long long w2 = *(const unsigned long long*)(wp + j * 256);
                    ffma2(accq, hp, w2);
                }
                unpk2(accq, lo, hi);
                acc2 = lo + hi;
            }
            if (rank == 0) {
                float* dst = g_hw + ((size_t)(b * (TT + 1) + t + 1)) * G3;
                dst[tid] = acc;
                hwfresh[tid] = acc;
                st_remote(mapa_rank(smem_u32(hwfresh + tid), 1u), acc);
                if (tid < 128) {
                    dst[256 + tid] = acc2;
                    hwfresh[256 + tid] = acc2;
                    st_remote(mapa_rank(smem_u32(hwfresh + 256 + tid), 1u), acc2);
                }
            } else {
                hcc_w[tid] = acc;
                st_remote(mapa_rank(smem_u32(hcc_w + tid), 0u), acc);
                if (tid < 128) {
                    hcc_w[256 + tid] = acc2;
                    st_remote(mapa_rank(smem_u32(hcc_w + 256 + tid), 0u), acc2);
                }
            }
        }
        CLUSTER_ARRIVE();

        // ---- Prefetch t+1 inside the sync window ---------------------------
        {
            int tn = (t + 1 < TT) ? t + 1 : t;
            psx = src_all[(b * TT + tn) * XX + xa];
            pfresh = (psx == t) && (tn == t + 1);   // row t+1 = hwfresh
            const float* wrow = g_wiw + ((size_t)((b * TT + tn) * XX + xa)) * G3;
            pwf0 = wrow[ha];        pwf1 = wrow[ha + 64];
            pwi0 = wrow[128 + ha];  pwi1 = wrow[128 + ha + 64];
            pwg0 = wrow[256 + ha];  pwg1 = wrow[256 + ha + 64];
            const float* cx = cs_out + ((size_t)(b * TT + psx)) * HH;
            pcx0 = cx[ha]; pcx1 = cx[ha + 64];
            pcv  = cnt_all[b * TT + tn];
            pawi = g_awi[((size_t)(b * TT + tn)) * HH + hq];
            const float* wic = g_wic + ((size_t)(b * TT + tn)) * G3;
            pc2i = wic[hq]; pc2o = wic[128 + hq]; pc2g = wic[256 + hq];
            if (!pfresh) {   // rows <= t: already globally visible
                const float* hwrow = g_hw + ((size_t)(b * (TT + 1) + psx + 1)) * G3;
                phf0 = hwrow[ha];        phf1 = hwrow[ha + 64];
                phi0 = hwrow[128 + ha];  phi1 = hwrow[128 + ha + 64];
                phg0 = hwrow[256 + ha];  phg1 = hwrow[256 + ha + 64];
            }
        }
        CLUSTER_WAIT();
    }
}

// ---------------------------------------------------------------------------
extern "C" void kernel_launch(void* const* d_in, const int* in_sizes, int n_in,
                              void* d_out, int out_size)
{
    const float *inp = nullptr, *skip_words = nullptr;
    const float *w_ih_c = nullptr, *w_hh_c = nullptr, *bias_c = nullptr;
    const float *a_ih = nullptr, *a_hh = nullptr, *a_bias = nullptr;
    const float *w_ih_w = nullptr, *w_hh_w = nullptr, *bias_w = nullptr;
    const int *skip_sources = nullptr, *skip_count = nullptr;

    int c49 = 0, c384 = 0, c16 = 0;
    for (int i = 0; i < n_in; ++i) {
        switch (in_sizes[i]) {
            case 4194304:  inp = (const float*)d_in[i]; break;
            case 33554432: skip_words = (const float*)d_in[i]; break;
            case 64:       break;
            case 262144:   skip_sources = (const int*)d_in[i]; break;
            case 32768:    skip_count = (const int*)d_in[i]; break;
            case 49152:
                if (c49 == 0) w_ih_c = (const float*)d_in[i];
                else if (c49 == 1) w_hh_c = (const float*)d_in[i];
                else if (c49 == 2) w_ih_w = (const float*)d_in[i];
                else w_hh_w = (const float*)d_in[i];
                ++c49; break;
            case 384:
                if (c384 == 0) bias_c = (const float*)d_in[i];
                else bias_w = (const float*)d_in[i];
                ++c384; break;
            case 16384:
                if (c16 == 0) a_ih = (const float*)d_in[i];
                else a_hh = (const float*)d_in[i];
                ++c16; break;
            case 128:      a_bias = (const float*)d_in[i]; break;
            default: break;
        }
    }

    void *p_wic = nullptr, *p_awi = nullptr, *p_wiw = nullptr;
    cudaGetSymbolAddress(&p_wic, g_wic);
    cudaGetSymbolAddress(&p_awi, g_awi);
    cudaGetSymbolAddress(&p_wiw, g_wiw);

    cudaFuncSetAttribute(gemm128_kernel,
                         cudaFuncAttributeMaxDynamicSharedMemorySize, 131072);
    cudaFuncSetAttribute(lattice_rec_kernel,
                         cudaFuncAttributeMaxDynamicSharedMemorySize,
                         SMEM_REC_FLOATS * (int)sizeof(float));

    gemm128_kernel<<<dim3(256, 3),  256, 131072>>>(inp, w_ih_c, bias_c,
                                                   (float*)p_wic, 384);
    gemm128_kernel<<<dim3(256, 1),  256, 131072>>>(inp, a_ih, a_bias,
                                                   (float*)p_awi, 128);
    gemm128_kernel<<<dim3(2048, 3), 256, 131072>>>(skip_words, w_ih_w, bias_w,
                                                   (float*)p_wiw, 384);

    lattice_rec_kernel<<<BB * 2, 256, SMEM_REC_FLOATS * sizeof(float)>>>(
        w_hh_w, w_hh_c, a_hh, skip_sources, skip_count, (float*)d_out);
}